// round 17
// baseline (speedup 1.0000x reference)
#include <cuda_runtime.h>
#include <cuda_bf16.h>
#include <math.h>
#include <stdint.h>

#define N_  4
#define T_  4096
#define D_  1024
#define H_  1536
#define M_  (N_*T_)       // 16384 rows
#define G2H (2*H_)        // 3072
#define TC  128           // scan chunk length == GEMM M-tile
#define NC  (T_/TC)       // 32 chunks

// -------- scratch (device globals; no allocation allowed) --------
__device__ __align__(256) float g_gx  [(size_t)M_*G2H];   // gate half = gelu(gate); B-half: boundary rows only
__device__ __align__(256) float g_alpha[(size_t)M_*H_];
__device__ __align__(256) float g_xs  [(size_t)M_*H_];
__device__ __align__(256) float g_cA  [N_*NC*H_];
__device__ __align__(256) float g_cB  [N_*NC*H_];
// activation bf16 hi/lo planes
__device__ __align__(256) __nv_bfloat16 g_xh [(size_t)M_*D_];
__device__ __align__(256) __nv_bfloat16 g_xl [(size_t)M_*D_];
__device__ __align__(256) __nv_bfloat16 g_xbh[(size_t)M_*H_];
__device__ __align__(256) __nv_bfloat16 g_xbl[(size_t)M_*H_];
__device__ __align__(256) __nv_bfloat16 g_yh [(size_t)M_*H_];
__device__ __align__(256) __nv_bfloat16 g_yl [(size_t)M_*H_];
// weight bf16 hi/lo planes
__device__ __align__(256) __nv_bfloat16 g_wih[(size_t)G2H*D_];
__device__ __align__(256) __nv_bfloat16 g_wil[(size_t)G2H*D_];
__device__ __align__(256) __nv_bfloat16 g_wgh[(size_t)G2H*H_];  // rows permuted for EPI2
__device__ __align__(256) __nv_bfloat16 g_wgl[(size_t)G2H*H_];
__device__ __align__(256) __nv_bfloat16 g_woh[(size_t)D_*H_];
__device__ __align__(256) __nv_bfloat16 g_wol[(size_t)D_*H_];

// ======================= helpers =======================
__device__ __forceinline__ uint32_t smem_u32(const void* p) {
    uint32_t a;
    asm("{ .reg .u64 t; cvta.to.shared.u64 t, %1; cvt.u32.u64 %0, t; }" : "=r"(a) : "l"(p));
    return a;
}
__device__ __forceinline__ void ldmx4(uint32_t* r, uint32_t a) {
    asm volatile("ldmatrix.sync.aligned.m8n8.x4.shared.b16 {%0,%1,%2,%3}, [%4];"
        : "=r"(r[0]), "=r"(r[1]), "=r"(r[2]), "=r"(r[3]) : "r"(a));
}
__device__ __forceinline__ void mma16816(float* d, const uint32_t* a, const uint32_t* b) {
    asm volatile("mma.sync.aligned.m16n8k16.row.col.f32.bf16.bf16.f32 "
        "{%0,%1,%2,%3}, {%4,%5,%6,%7}, {%8,%9}, {%0,%1,%2,%3};"
        : "+f"(d[0]), "+f"(d[1]), "+f"(d[2]), "+f"(d[3])
        : "r"(a[0]), "r"(a[1]), "r"(a[2]), "r"(a[3]), "r"(b[0]), "r"(b[1]));
}
__device__ __forceinline__ void cpa16(uint32_t dst, const void* src) {
    asm volatile("cp.async.cg.shared.global [%0], [%1], 16;" :: "r"(dst), "l"(src));
}
#define CP_COMMIT()     asm volatile("cp.async.commit_group;" ::: "memory")
#define CP_WAIT(NN)     asm volatile("cp.async.wait_group %0;" :: "n"(NN) : "memory")
__device__ __forceinline__ float sigmoidf_(float v) { return 1.f / (1.f + expf(-v)); }
__device__ __forceinline__ void split_bf(float v, __nv_bfloat16& h, __nv_bfloat16& l) {
    h = __float2bfloat16(v);
    l = __float2bfloat16(v - __bfloat162float(h));
}

// ================== bf16x3 mma GEMM (all cp.async, 3-stage, swizzled) ==================
#define PL_A_H 0
#define PL_A_L 8192
#define PL_B_H 16384
#define PL_B_L 24576
#define BLO    (PL_B_L - PL_B_H)
#define STAGE  32768
#define GEMM_SMEM (3*STAGE)   // 98304

__device__ __forceinline__ int swz16(int row) {
    return ((row & 3) ^ ((row >> 2) & 3));
}

// persistent per-thread load pointers (hi planes only; lo = hi + delta)
struct LoadPtrs {
    const __nv_bfloat16 *a0, *a1, *b0, *b1;
    uint32_t so0, so1;
};

__device__ __forceinline__ LoadPtrs make_ptrs(int tid, int K,
    const __nv_bfloat16* Ah, const __nv_bfloat16* Bh)
{
    LoadPtrs p;
    const int col = tid & 3;
    const int r0 = tid >> 2, r1 = (tid + 256) >> 2;
    const size_t g0 = (size_t)r0 * K + col * 8;
    const size_t g1 = (size_t)r1 * K + col * 8;
    p.a0 = Ah + g0;  p.a1 = Ah + g1;
    p.b0 = Bh + g0;  p.b1 = Bh + g1;
    p.so0 = (uint32_t)(r0 * 64 + ((col ^ swz16(r0)) << 4));
    p.so1 = (uint32_t)(r1 * 64 + ((col ^ swz16(r1)) << 4));
    return p;
}

__device__ __forceinline__ void issue_chunk(uint32_t stg, LoadPtrs& p,
                                            ptrdiff_t dA, ptrdiff_t dB) {
    cpa16(stg + PL_A_H + p.so0, p.a0);
    cpa16(stg + PL_A_L + p.so0, p.a0 + dA);
    cpa16(stg + PL_B_H + p.so0, p.b0);
    cpa16(stg + PL_B_L + p.so0, p.b0 + dB);
    cpa16(stg + PL_A_H + p.so1, p.a1);
    cpa16(stg + PL_A_L + p.so1, p.a1 + dA);
    cpa16(stg + PL_B_H + p.so1, p.b1);
    cpa16(stg + PL_B_L + p.so1, p.b1 + dB);
    p.a0 += 32; p.a1 += 32; p.b0 += 32; p.b1 += 32;
}

// one MMA bundle: 4 n-tiles (ntb..ntb+3) x 2 m-tiles x 3 split-MMAs
__device__ __forceinline__ void mma_bundle(float acc[2][8][4],
    const uint32_t ah[2][4], const uint32_t al[2][4],
    const uint32_t bh[2][4], const uint32_t bl[2][4], int ntb)
{
#pragma unroll
    for (int mt = 0; mt < 2; mt++)
#pragma unroll
        for (int j = 0; j < 4; j++) {
            const uint32_t* bph = &bh[j >> 1][(j & 1) * 2];
            const uint32_t* bpl = &bl[j >> 1][(j & 1) * 2];
            mma16816(acc[mt][ntb + j], ah[mt], bph);
            mma16816(acc[mt][ntb + j], ah[mt], bpl);
            mma16816(acc[mt][ntb + j], al[mt], bph);
        }
}

// EPI: 0 = plain, 1 = GEMM1 (gate: gelu; B-half: fused conv), 2 = fused ew + chunk-scan
template<int EPI>
__global__ __launch_bounds__(256, 2)
void gemm_mma(const __nv_bfloat16* __restrict__ Ah, const __nv_bfloat16* __restrict__ Al,
              const __nv_bfloat16* __restrict__ Bh, const __nv_bfloat16* __restrict__ Bl,
              float* __restrict__ C,
              const __nv_bfloat16* __restrict__ xbh, const __nv_bfloat16* __restrict__ xbl,
              const float* __restrict__ bg, const float* __restrict__ fbase,
              float* __restrict__ alpha_o, float* __restrict__ xs_o,
              const float* __restrict__ cw_, const float* __restrict__ cb_,
              __nv_bfloat16* __restrict__ oxh, __nv_bfloat16* __restrict__ oxl,
              int K, int ldc)
{
    extern __shared__ char sm[];
    const int tid = threadIdx.x;
    const int lid = tid & 31, wid = tid >> 5;
    const int wm = wid >> 1, wn = wid & 1;
    const int bm = blockIdx.y * 128;
    const int bn = blockIdx.x * 128;

    const ptrdiff_t dA = Al - Ah;
    const ptrdiff_t dB = Bl - Bh;
    LoadPtrs lp = make_ptrs(tid, K, Ah + (size_t)bm * K, Bh + (size_t)bn * K);

    float acc[2][8][4];
#pragma unroll
    for (int i = 0; i < 2; i++)
#pragma unroll
        for (int j = 0; j < 8; j++)
#pragma unroll
            for (int q = 0; q < 4; q++) acc[i][j][q] = 0.f;

    const uint32_t sb = smem_u32(sm);
    const int arow = wm * 32 + (lid & 15);
    const int brow = wn * 64 + (lid & 7) + ((lid >> 4) & 1) * 8;
    const uint32_t ax = (uint32_t)((((lid >> 4) & 1) << 4) ^ (swz16(arow) << 4));
    const uint32_t bx = (uint32_t)((((lid >> 3) & 1) << 4) ^ (swz16(brow) << 4));
    const uint32_t aB0 = sb + (uint32_t)(arow * 64);
    const uint32_t bB0 = sb + PL_B_H + (uint32_t)(brow * 64);

    const int KT = K >> 5;
    issue_chunk(sb, lp, dA, dB);
    CP_COMMIT();
    issue_chunk(sb + STAGE, lp, dA, dB);
    CP_COMMIT();

    int stg = 0;
    for (int c = 0; c < KT; c++) {
        if (c + 1 < KT) { CP_WAIT(1); } else { CP_WAIT(0); }
        __syncthreads();
        const uint32_t so = (uint32_t)(stg * STAGE);
        const uint32_t aBs = aB0 + so, bBs = bB0 + so;

        uint32_t ah[2][4], al[2][4], ah2[2][4], al2[2][4];
        uint32_t bh[2][4], bl[2][4];
        // ---- kt0: interleaved loads (first-consumed fragments first) ----
        ldmx4(ah[0], aBs + ax);
        ldmx4(bh[0], bBs + bx);
        ldmx4(ah[1], aBs + 1024 + ax);
        ldmx4(bh[1], bBs + 1024 + bx);
        ldmx4(bl[0], bBs + BLO + bx);
        ldmx4(bl[1], bBs + BLO + 1024 + bx);
        ldmx4(al[0], aBs + PL_A_L + ax);
        ldmx4(al[1], aBs + PL_A_L + 1024 + ax);
        mma_bundle(acc, ah, al, bh, bl, 0);
        // ---- kt0: B half1 (reuse bh/bl regs) + prefetch A-hi of kt1 ----
        ldmx4(bh[0], bBs + 2048 + bx);     ldmx4(bh[1], bBs + 3072 + bx);
        ldmx4(bl[0], bBs + BLO + 2048 + bx); ldmx4(bl[1], bBs + BLO + 3072 + bx);
        ldmx4(ah2[0], aBs + (32u ^ ax));   ldmx4(ah2[1], aBs + 1024 + (32u ^ ax));
        mma_bundle(acc, ah, al, bh, bl, 4);
        if (c + 2 < KT) {
            int ns = stg + 2; if (ns >= 3) ns -= 3;
            issue_chunk(sb + ns * STAGE, lp, dA, dB);
            CP_COMMIT();
        }
        // ---- kt1: B half0 first (consumed before A-lo), then A-lo ----
        ldmx4(bh[0], bBs + (32u ^ bx));           ldmx4(bh[1], bBs + 1024 + (32u ^ bx));
        ldmx4(bl[0], bBs + BLO + (32u ^ bx));     ldmx4(bl[1], bBs + BLO + 1024 + (32u ^ bx));
        ldmx4(al2[0], aBs + PL_A_L + (32u ^ ax)); ldmx4(al2[1], aBs + PL_A_L + 1024 + (32u ^ ax));
        mma_bundle(acc, ah2, al2, bh, bl, 0);
        // ---- kt1: B half1 ----
        ldmx4(bh[0], bBs + 2048 + (32u ^ bx));    ldmx4(bh[1], bBs + 3072 + (32u ^ bx));
        ldmx4(bl[0], bBs + BLO + 2048 + (32u ^ bx)); ldmx4(bl[1], bBs + BLO + 3072 + (32u ^ bx));
        mma_bundle(acc, ah2, al2, bh, bl, 4);
        if (++stg == 3) stg = 0;
    }

    const int r0 = bm + wm * 32 + (lid >> 2);

    if (EPI == 2) {
        const int hloc = wn * 32 + (lid & 3);
        const int h0 = (bn >> 1);
        float sp8[8], bgf[8], bgi[8];
#pragma unroll
        for (int nt = 0; nt < 8; nt++) {
            int h = h0 + hloc + nt * 4;
            float fb = fbase[h];
            sp8[nt] = fmaxf(fb, 0.f) + log1pf(expf(-fabsf(fb)));
            bgf[nt] = bg[h]; bgi[nt] = bg[H_ + h];
        }
        const int rloc0 = wm * 32 + (lid >> 2);
#pragma unroll
        for (int mt = 0; mt < 2; mt++)
#pragma unroll
            for (int nt = 0; nt < 8; nt++)
#pragma unroll
                for (int half = 0; half < 2; half++) {
                    int rl = rloc0 + mt * 16 + half * 8;
                    float forget = acc[mt][nt][half * 2 + 0] + bgf[nt];
                    float inp    = acc[mt][nt][half * 2 + 1] + bgi[nt];
                    float a = expf(-8.f * sp8[nt] * sigmoidf_(forget));
                    float beta = sqrtf(1.f - a * a + 1e-6f);
                    size_t ix = (size_t)(bm + rl) * H_ + h0 + hloc + nt * 4;
                    float xb = __bfloat162float(xbh[ix]) + __bfloat162float(xbl[ix]);
                    acc[mt][nt][half * 2 + 0] = a;
                    acc[mt][nt][half * 2 + 1] = beta * sigmoidf_(inp) * xb;
                }
        float* st_a = (float*)sm;
        float* st_x = (float*)sm + 128 * 68;
        __syncthreads();
#pragma unroll
        for (int mt = 0; mt < 2; mt++)
#pragma unroll
            for (int nt = 0; nt < 8; nt++)
#pragma unroll
                for (int half = 0; half < 2; half++) {
                    int rl = rloc0 + mt * 16 + half * 8;
                    st_a[rl * 68 + hloc + nt * 4] = acc[mt][nt][half * 2 + 0];
                    st_x[rl * 68 + hloc + nt * 4] = acc[mt][nt][half * 2 + 1];
                }
        __syncthreads();
#pragma unroll
        for (int it = 0; it < 8; it++) {
            int idx = it * 256 + tid;
            int row = idx >> 4, cc = (idx & 15) * 4;
            float4 va = *(float4*)&st_a[row * 68 + cc];
            float4 vx = *(float4*)&st_x[row * 68 + cc];
            *(float4*)&alpha_o[(size_t)(bm + row) * H_ + h0 + cc] = va;
            *(float4*)&xs_o   [(size_t)(bm + row) * H_ + h0 + cc] = vx;
        }
        if (tid < 64) {
            float A = 1.f, Bv = 0.f;
#pragma unroll 4
            for (int t = 0; t < 128; t++) {
                float a = st_a[t * 68 + tid];
                float xv = st_x[t * 68 + tid];
                Bv = fmaf(a, Bv, xv);
                A *= a;
            }
            int n = bm >> 12;
            int cch = (bm & (T_ - 1)) >> 7;
            int ci = (n * NC + cch) * H_ + h0 + tid;
            g_cA[ci] = A;
            g_cB[ci] = Bv;
        }
        return;
    }

    if (EPI == 1 && bn >= H_) {
        float* st = (float*)sm;
        const int rl0 = wm * 32 + (lid >> 2);
        const int cl0 = wn * 64 + (lid & 3) * 2;
        __syncthreads();
#pragma unroll
        for (int mt = 0; mt < 2; mt++)
#pragma unroll
            for (int nt = 0; nt < 8; nt++)
#pragma unroll
                for (int half = 0; half < 2; half++) {
                    int rl = rl0 + mt * 16 + half * 8;
                    int cl = cl0 + nt * 8;
                    st[rl * 132 + cl]     = acc[mt][nt][half * 2 + 0];
                    st[rl * 132 + cl + 1] = acc[mt][nt][half * 2 + 1];
                }
        __syncthreads();
        const int hb = bn - H_;
        {
            int i = tid;
#pragma unroll
            for (int it = 0; it < 3; it++, i += 256) {
                int ri = i >> 7;
                int cc = i & 127;
                int row = (ri < 3) ? ri : (122 + ri);
                C[(size_t)(bm + row) * ldc + H_ + hb + cc] = st[row * 132 + cc];
            }
        }
        const int c = tid & 127;
        const int h = hb + c;
        const float w0 = cw_[h * 4 + 0], w1 = cw_[h * 4 + 1];
        const float w2 = cw_[h * 4 + 2], w3 = cw_[h * 4 + 3];
        const float bb = cb_[h];
        for (int r = 3 + (tid >> 7); r < 128; r += 2) {
            float a = bb;
            a = fmaf(w0, st[(r - 3) * 132 + c], a);
            a = fmaf(w1, st[(r - 2) * 132 + c], a);
            a = fmaf(w2, st[(r - 1) * 132 + c], a);
            a = fmaf(w3, st[(r - 0) * 132 + c], a);
            __nv_bfloat16 hi, lo;
            split_bf(a, hi, lo);
            size_t ox = (size_t)(bm + r) * H_ + h;
            oxh[ox] = hi;
            oxl[ox] = lo;
        }
        return;
    }

    const bool dg = (EPI == 1);
    const int cbase = bn + wn * 64 + (lid & 3) * 2;
#pragma unroll
    for (int mt = 0; mt < 2; mt++) {
        const int row = r0 + mt * 16;
#pragma unroll
        for (int nt = 0; nt < 8; nt++) {
            const int col = cbase + nt * 8;
            float2 v0 = make_float2(acc[mt][nt][0], acc[mt][nt][1]);
            float2 v1 = make_float2(acc[mt][nt][2], acc[mt][nt][3]);
            if (dg) {
                v0.x = 0.5f * v0.x * (1.f + erff(v0.x * 0.70710678118654752f));
                v0.y = 0.5f * v0.y * (1.f + erff(v0.y * 0.70710678118654752f));
                v1.x = 0.5f * v1.x * (1.f + erff(v1.x * 0.70710678118654752f));
                v1.y = 0.5f * v1.y * (1.f + erff(v1.y * 0.70710678118654752f));
            }
            *(float2*)(C + (size_t)row * ldc + col) = v0;
            *(float2*)(C + (size_t)(row + 8) * ldc + col) = v1;
        }
    }
}

// -------- conv boundary rows --------
__global__ void conv_boundary(const float* __restrict__ cw, const float* __restrict__ cb)
{
    int idx = blockIdx.x * blockDim.x + threadIdx.x;
    if (idx >= (M_ / 128) * 3 * H_) return;
    int h = idx % H_;
    int q = idx / H_;
    int r = q % 3;
    int tile = q / 3;
    int m = tile * 128 + r;
    int n = m / T_, t = m % T_;
    float a = cb[h];
#pragma unroll
    for (int k = 0; k < 4; k++) {
        int tt = t - 3 + k;
        if (tt >= 0)
            a = fmaf(cw[h * 4 + k], g_gx[(size_t)(n * T_ + tt) * G2H + H_ + h], a);
    }
    __nv_bfloat16 hi, lo;
    split_bf(a, hi, lo);
    g_xbh[(size_t)m * H_ + h] = hi;
    g_xbl[(size_t)m * H_ + h] = lo;
}

// -------- unified pack kernel --------
#define PK_X   ((long long)M_*D_/8)
#define PK_WI  ((long long)G2H*D_/8)
#define PK_WG  ((long long)G2H*H_/8)
#define PK_WO  ((long long)D_*H_/8)
__global__ void pack_all(const float* __restrict__ x, const float* __restrict__ wi,
                         const float* __restrict__ wg, const float* __restrict__ wo)
{
    long long i = (long long)blockIdx.x * blockDim.x + threadIdx.x;
    const float* s; __nv_bfloat16 *hi, *lo; long long off8;
    bool permute = false;
    if (i < PK_X) { s = x; hi = g_xh; lo = g_xl; off8 = i; }
    else if ((i -= PK_X) < PK_WI) { s = wi; hi = g_wih; lo = g_wil; off8 = i; }
    else if ((i -= PK_WI) < PK_WG) { s = wg; hi = g_wgh; lo = g_wgl; off8 = i; permute = true; }
    else if ((i -= PK_WG) < PK_WO) { s = wo; hi = g_woh; lo = g_wol; off8 = i; }
    else return;

    long long dste = off8 * 8;
    long long srce;
    if (permute) {
        long long r = dste / H_;
        long long cc = dste - r * H_;
        srce = ((r & 1) * H_ + (r >> 1)) * (long long)H_ + cc;
    } else srce = dste;

#pragma unroll
    for (int half = 0; half < 2; half++) {
        float4 f = *(const float4*)(s + srce + half * 4);
        __nv_bfloat16 h[4], l[4];
        split_bf(f.x, h[0], l[0]); split_bf(f.y, h[1], l[1]);
        split_bf(f.z, h[2], l[2]); split_bf(f.w, h[3], l[3]);
        *(uint2*)(hi + dste + half * 4) = *(uint2*)h;
        *(uint2*)(lo + dste + half * 4) = *(uint2*)l;
    }
}

// -------- scan replay with inline carry --------
__global__ void scan_p3()
{
    int h = blockIdx.x * 128 + threadIdx.x;
    int c = blockIdx.y, n = blockIdx.z;
    float carry = 0.f;
    for (int cc = 0; cc < c; cc++) {
        int i = (n * NC + cc) * H_ + h;
        carry = fmaf(g_cA[i], carry, g_cB[i]);
    }
    size_t base  = ((size_t)(n * T_ + c * TC)) * H_ + h;
    size_t gbase = ((size_t)(n * T_ + c * TC)) * G2H + h;
    float hp = carry;
#pragma unroll 8
    for (int t = 0; t < TC; t++) {
        float a = g_alpha[base + (size_t)t * H_];
        float x = g_xs   [base + (size_t)t * H_];
        hp = fmaf(a, hp, x);
        float g = g_gx[gbase + (size_t)t * G2H];
        float v = hp * g;
        __nv_bfloat16 hi, lo;
        split_bf(v, hi, lo);
        g_yh[base + (size_t)t * H_] = hi;
        g_yl[base + (size_t)t * H_] = lo;
    }
}

// -------- launch --------
extern "C" void kernel_launch(void* const* d_in, const int* in_sizes, int n_in,
                              void* d_out, int out_size)
{
    const float* x      = (const float*)d_in[0];
    const float* W_in   = (const float*)d_in[1];
    const float* conv_w = (const float*)d_in[2];
    const float* conv_b = (const float*)d_in[3];
    const float* W_g    = (const float*)d_in[4];
    const float* b_g    = (const float*)d_in[5];
    const float* fbase  = (const float*)d_in[6];
    const float* W_out  = (const float*)d_in[7];
    float* out = (float*)d_out;

    float *gx, *alp, *xs;
    __nv_bfloat16 *xh, *xl, *xbh, *xbl, *yh, *yl, *wih, *wil, *wgh, *wgl, *woh, *wol;
    cudaGetSymbolAddress((void**)&gx,  g_gx);
    cudaGetSymbolAddress((void**)&alp, g_alpha);
    cudaGetSymbolAddress((void**)&xs,  g_xs);
    cudaGetSymbolAddress((void**)&xh,  g_xh);
    cudaGetSymbolAddress((void**)&xl,  g_xl);
    cudaGetSymbolAddress((void**)&xbh, g_xbh);
    cudaGetSymbolAddress((void**)&xbl, g_xbl);
    cudaGetSymbolAddress((void**)&yh,  g_yh);
    cudaGetSymbolAddress((void**)&yl,  g_yl);
    cudaGetSymbolAddress((void**)&wih, g_wih);
    cudaGetSymbolAddress((void**)&wil, g_wil);
    cudaGetSymbolAddress((void**)&wgh, g_wgh);
    cudaGetSymbolAddress((void**)&wgl, g_wgl);
    cudaGetSymbolAddress((void**)&woh, g_woh);
    cudaGetSymbolAddress((void**)&wol, g_wol);

    cudaFuncSetAttribute(gemm_mma<0>, cudaFuncAttributeMaxDynamicSharedMemorySize, GEMM_SMEM);
    cudaFuncSetAttribute(gemm_mma<1>, cudaFuncAttributeMaxDynamicSharedMemorySize, GEMM_SMEM);
    cudaFuncSetAttribute(gemm_mma<2>, cudaFuncAttributeMaxDynamicSharedMemorySize, GEMM_SMEM);

    // 0) pack x + weights (single kernel)
    {
        long long total = PK_X + PK_WI + PK_WG + PK_WO;
        pack_all<<<(int)((total + 255) / 256), 256>>>(x, W_in, W_g, W_out);
    }
    // 1) gx = x @ W_in^T; gate: gelu; B-half: fused conv -> xb planes
    gemm_mma<1><<<dim3(G2H/128, M_/128), 256, GEMM_SMEM>>>(
        xh, xl, wih, wil, gx, nullptr, nullptr, nullptr, nullptr, nullptr, nullptr,
        conv_w, conv_b, xbh, xbl, D_, G2H);
    // 1b) conv boundary rows
    conv_boundary<<<((M_/128)*3*H_ + 255)/256, 256>>>(conv_w, conv_b);
    // 2) fused ew GEMM -> alpha, xs, chunk-scan reduction
    gemm_mma<2><<<dim3(G2H/128, M_/128), 256, GEMM_SMEM>>>(
        xbh, xbl, wgh, wgl, nullptr, xbh, xbl, b_g, fbase, alp, xs,
        nullptr, nullptr, nullptr, nullptr, H_, 0);
    // 3) scan replay (carry fused in)
    scan_p3<<<dim3(H_/128, NC, N_), 128>>>();
    // 4) out = (gelu(gate)*h) @ W_out^T
    gemm_mma<0><<<dim3(D_/128, M_/128), 256, GEMM_SMEM>>>(
        yh, yl, woh, wol, out, nullptr, nullptr, nullptr, nullptr, nullptr, nullptr,
        nullptr, nullptr, nullptr, nullptr, H_, D_);
}